// round 9
// baseline (speedup 1.0000x reference)
#include <cuda_runtime.h>
#include <cuda_bf16.h>

#define N_NODESC 50000
#define N_EDGESC 400000
#define SCAN_BLKS 49   // ceil(50000/1024)

typedef unsigned int u32;
typedef unsigned long long u64;

// ---------------- device scratch ----------------
__device__ u64   g_xs[(size_t)N_NODESC * 64];     // x split: [row][pair] (hi|lo packed u64)
__device__ float g_Aarr[(size_t)N_NODESC * 256];  // A-half of edge pre-act (+b_edge)
__device__ float g_Barr[(size_t)N_NODESC * 256];  // B-half (gathered randomly; L2-resident)
__device__ u64   g_nas[(size_t)N_NODESC * 64];    // node_agg split
__device__ u64   g_eas[(size_t)N_NODESC * 128];   // edge_agg split
__device__ u64   g_hs[(size_t)N_NODESC * 192];    // h split
__device__ float g_h2[(size_t)N_NODESC * 32];
__device__ u64   g_Wcs[64 * 512];                 // Wc split  [pair][n]
__device__ u64   g_Wns[64 * 256];
__device__ u64   g_Wes[128 * 128];
__device__ u64   g_Wfs[192 * 32];
__device__ float g_bc[512];
__device__ int   g_count[N_NODESC];
__device__ int   g_off[N_NODESC + 1];
__device__ int   g_cur[N_NODESC];
__device__ int   g_csr[N_EDGESC];
__device__ int   g_ei32[2 * N_EDGESC];
__device__ int   g_bsum[SCAN_BLKS];
__device__ int   g_bpre[SCAN_BLKS];
__device__ int   g_dtype_flag;

// ---------------- helpers ----------------
__device__ __forceinline__ u64 splitpair(float a, float b) {
    __nv_bfloat162 h = __float22bfloat162_rn(make_float2(a, b));
    float2 hf = __bfloat1622float2(h);
    __nv_bfloat162 l = __float22bfloat162_rn(make_float2(a - hf.x, b - hf.y));
    u32 hw = *(u32*)&h, lw = *(u32*)&l;
    return (u64)hw | ((u64)lw << 32);
}

__device__ __forceinline__ void mma16816(float* d, const u32* a, const u32* b) {
    asm volatile(
        "mma.sync.aligned.m16n8k16.row.col.f32.bf16.bf16.f32 "
        "{%0,%1,%2,%3}, {%4,%5,%6,%7}, {%8,%9}, {%0,%1,%2,%3};\n"
        : "+f"(d[0]), "+f"(d[1]), "+f"(d[2]), "+f"(d[3])
        : "r"(a[0]), "r"(a[1]), "r"(a[2]), "r"(a[3]), "r"(b[0]), "r"(b[1]));
}

// 16-byte cp.async (cg = L2 path). pred=false -> zero-fill.
__device__ __forceinline__ void cpasync16(u32 saddr, const void* g, bool pred) {
    int sz = pred ? 16 : 0;
    asm volatile("cp.async.cg.shared.global [%0], [%1], 16, %2;\n"
                 :: "r"(saddr), "l"(g), "r"(sz));
}
#define CP_COMMIT() asm volatile("cp.async.commit_group;\n")
#define CP_WAIT1()  asm volatile("cp.async.wait_group 1;\n")

// ---------------- init / dtype detect / convert+hist ----------------
__global__ void zero_init_kernel() {
    int i = blockIdx.x * blockDim.x + threadIdx.x;
    if (i < N_NODESC) g_count[i] = 0;
    if (i == 0) g_dtype_flag = 0;
}

__global__ void detect_kernel(const int* __restrict__ w) {
    int acc = 0;
    for (int i = blockIdx.x * blockDim.x + threadIdx.x; i < N_EDGESC; i += gridDim.x * blockDim.x)
        acc |= w[2 * i + 1];
    #pragma unroll
    for (int o = 16; o; o >>= 1) acc |= __shfl_xor_sync(0xffffffffu, acc, o);
    if ((threadIdx.x & 31) == 0 && acc) atomicOr(&g_dtype_flag, 1);
}

__global__ void conv_hist_kernel(const void* __restrict__ ei) {
    int e = blockIdx.x * blockDim.x + threadIdx.x;
    if (e < N_EDGESC) {
        int s, d;
        if (g_dtype_flag) {
            s = ((const int*)ei)[e];
            d = ((const int*)ei)[N_EDGESC + e];
        } else {
            s = (int)((const long long*)ei)[e];
            d = (int)((const long long*)ei)[N_EDGESC + e];
        }
        g_ei32[e] = s;
        g_ei32[N_EDGESC + e] = d;
        atomicAdd(&g_count[d], 1);
    }
}

// ---------------- parallel scan ----------------
__global__ void scan1_kernel() {
    __shared__ int wsum[32], wpre[32];
    int tid = threadIdx.x, lane = tid & 31, w = tid >> 5;
    int i = blockIdx.x * 1024 + tid;
    int orig = (i < N_NODESC) ? g_count[i] : 0;
    int v = orig;
    #pragma unroll
    for (int o = 1; o < 32; o <<= 1) {
        int t = __shfl_up_sync(0xffffffffu, v, o);
        if (lane >= o) v += t;
    }
    if (lane == 31) wsum[w] = v;
    __syncthreads();
    if (w == 0) {
        int s = wsum[lane], sv = s;
        #pragma unroll
        for (int o = 1; o < 32; o <<= 1) {
            int t = __shfl_up_sync(0xffffffffu, sv, o);
            if (lane >= o) sv += t;
        }
        wpre[lane] = sv - s;
        if (lane == 31) g_bsum[blockIdx.x] = sv;
    }
    __syncthreads();
    if (i < N_NODESC) {
        int ex = wpre[w] + v - orig;
        g_off[i] = ex;
        g_cur[i] = ex;
    }
}

__global__ void scan2_kernel() {
    __shared__ int s[64];
    int tid = threadIdx.x;
    int orig = (tid < SCAN_BLKS) ? g_bsum[tid] : 0;
    s[tid] = orig;
    __syncthreads();
    #pragma unroll
    for (int o = 1; o < 64; o <<= 1) {
        int t = (tid >= o) ? s[tid - o] : 0;
        __syncthreads();
        s[tid] += t;
        __syncthreads();
    }
    if (tid < SCAN_BLKS) g_bpre[tid] = s[tid] - orig;
    if (tid == 63) g_off[N_NODESC] = s[63];
}

__global__ void scan3_kernel() {
    int i = blockIdx.x * blockDim.x + threadIdx.x;
    if (i < N_NODESC) {
        int add = g_bpre[i >> 10];
        g_off[i] += add;
        g_cur[i] += add;
    }
}

__global__ void scatter_kernel() {
    int e = blockIdx.x * blockDim.x + threadIdx.x;
    if (e < N_EDGESC) {
        int d = g_ei32[N_EDGESC + e];
        int s = g_ei32[e];
        int p = atomicAdd(&g_cur[d], 1);
        g_csr[p] = s;
    }
}

// ---------------- weight prep ----------------
__device__ __forceinline__ float wcval(const float* We, int k, int n) {
    return (n < 256) ? (We[k * 256 + n] - We[(128 + k) * 256 + n])
                     : We[(128 + k) * 256 + (n - 256)];
}

__global__ void prep_w_kernel(const float* __restrict__ We, const float* __restrict__ be,
                              const float* __restrict__ Wn, const float* __restrict__ Wd,
                              const float* __restrict__ Wf) {
    int idx = blockIdx.x * blockDim.x + threadIdx.x;   // 0 .. 32767
    {
        int c = idx >> 9, n = idx & 511;
        g_Wcs[idx] = splitpair(wcval(We, 2 * c, n), wcval(We, 2 * c + 1, n));
    }
    if (idx < 64 * 256) {
        int c = idx >> 8, n = idx & 255;
        g_Wns[idx] = splitpair(Wn[2 * c * 256 + n], Wn[(2 * c + 1) * 256 + n]);
    }
    if (idx < 128 * 128) {
        int c = idx >> 7, n = idx & 127;
        g_Wes[idx] = splitpair(Wd[2 * c * 128 + n], Wd[(2 * c + 1) * 128 + n]);
    }
    if (idx < 192 * 32) {
        int c = idx >> 5, n = idx & 31;
        g_Wfs[idx] = splitpair(Wf[2 * c * 32 + n], Wf[(2 * c + 1) * 32 + n]);
    }
    if (idx < 512) g_bc[idx] = (idx < 256) ? be[idx] : 0.0f;
}

__global__ void split_x_kernel(const float* __restrict__ x) {
    int idx = blockIdx.x * blockDim.x + threadIdx.x;
    if (idx < N_NODESC * 64) {
        int row = idx >> 6, c = idx & 63;
        float2 v = *(const float2*)(x + (size_t)row * 128 + 2 * c);
        g_xs[idx] = splitpair(v.x, v.y);
    }
}

// ---------------- A-panel-resident tensor-core GEMM ----------------
// Whole A panel (full K) loaded once into smem; W panels stream through a
// small double buffer while the block loops over NFULL/128 n-tiles.
// A panel [row][Kp+4]: (Kp+4) ≡ 4 mod 16 -> frag LDS.64 conflict-free.
// W buf [c][132]: cp.async contiguous; frag reads (4c+n) mod 16 distinct.
// OMODE: 0 = fp32 out, 1 = split-u64 out, 2 = AB dual fp32 (Aarr/Barr)
template <int BM, int WM, int WN, int K, int NFULL, bool RELU, int OMODE>
__global__ __launch_bounds__(256, 2) void mma_gemm_ares(
    const u64* __restrict__ As,      // [M][K/2]
    const u64* __restrict__ Ws,      // [K/2][NFULL]
    const float* __restrict__ bias,
    float* __restrict__ outf, u64* __restrict__ outs, float* __restrict__ outf2,
    int ldo_p, int ocol0, int M)
{
    constexpr int BN = 128;
    constexpr int Kp = K / 2;
    constexpr int KS = K / 16;               // k16 stages per n-tile
    constexpr int NTILES = NFULL / BN;
    constexpr int TS = NTILES * KS;          // total W stages
    constexpr int SRA = Kp + 4;              // ≡ 4 mod 16
    constexpr int SRW = BN + 4;
    constexpr int WARPS_N = BN / WN;
    constexpr int MT = WM / 16, NTw = WN / 8;
    static_assert((BM / WM) * (BN / WN) == 8, "warp grid must cover tile");
    constexpr int A_OPS = BM * (Kp / 2);     // 16B ops for the whole A panel
    constexpr int W_OPS = 8 * BN / 2;        // 16B ops per W stage (8 pairs)

    extern __shared__ u64 dsm[];
    u64* Apan = dsm;                         // [BM][SRA]
    u64* Wbuf = dsm + BM * SRA;              // [2][8][SRW]

    int tid = threadIdx.x;
    int w = tid >> 5, lane = tid & 31;
    int gr = lane >> 2, thc = lane & 3;
    int wm = w / WARPS_N, wn = w % WARPS_N;
    int m0 = blockIdx.x * BM;
    int m0w = wm * WM, n0w = wn * WN;

    // ---- load whole A panel (one commit group) ----
    #pragma unroll
    for (int j = 0; j < (A_OPS + 255) / 256; j++) {
        int p = tid + j * 256;
        if ((A_OPS % 256 == 0) || p < A_OPS) {
            int row = p / (Kp / 2), dc = (p % (Kp / 2)) * 2;
            u32 sa = (u32)__cvta_generic_to_shared(&Apan[row * SRA + dc]);
            cpasync16(sa, As + (size_t)(m0 + row) * Kp + dc, (m0 + row) < M);
        }
    }
    CP_COMMIT();

    auto issue_w = [&](int buf, int s) {
        int nt = s / KS, ks = s % KS;
        int p0 = ks * 8, n0 = nt * BN;
        #pragma unroll
        for (int j = 0; j < (W_OPS + 255) / 256; j++) {
            int p = tid + j * 256;
            if ((W_OPS % 256 == 0) || p < W_OPS) {
                int c = p / (BN / 2), dn = (p % (BN / 2)) * 2;
                u32 sa = (u32)__cvta_generic_to_shared(&Wbuf[(size_t)buf * 8 * SRW + c * SRW + dn]);
                cpasync16(sa, Ws + (size_t)(p0 + c) * NFULL + n0 + dn, true);
            }
        }
        CP_COMMIT();
    };

    issue_w(0, 0);

    float d[MT][NTw][4] = {};

    for (int s = 0; s < TS; s++) {
        int buf = s & 1;
        if (s + 1 < TS) issue_w(buf ^ 1, s + 1);
        else CP_COMMIT();            // empty group so wait_group 1 drains stage s (and A panel)
        CP_WAIT1();
        __syncthreads();

        int ks = s % KS;
        int kcol = ks * 8;

        u32 ah[MT][4], al[MT][4], bh[NTw][2], bl[NTw][2];
        #pragma unroll
        for (int i = 0; i < MT; i++) {
            int r0 = m0w + 16 * i + gr, r1 = r0 + 8;
            u64 v0 = Apan[r0 * SRA + kcol + thc],     v1 = Apan[r1 * SRA + kcol + thc];
            u64 v2 = Apan[r0 * SRA + kcol + thc + 4], v3 = Apan[r1 * SRA + kcol + thc + 4];
            ah[i][0] = (u32)v0; al[i][0] = (u32)(v0 >> 32);
            ah[i][1] = (u32)v1; al[i][1] = (u32)(v1 >> 32);
            ah[i][2] = (u32)v2; al[i][2] = (u32)(v2 >> 32);
            ah[i][3] = (u32)v3; al[i][3] = (u32)(v3 >> 32);
        }
        const u64* wb = Wbuf + (size_t)buf * 8 * SRW;
        #pragma unroll
        for (int j = 0; j < NTw; j++) {
            int nn = n0w + 8 * j + gr;
            u64 v0 = wb[thc * SRW + nn], v1 = wb[(thc + 4) * SRW + nn];
            bh[j][0] = (u32)v0; bl[j][0] = (u32)(v0 >> 32);
            bh[j][1] = (u32)v1; bl[j][1] = (u32)(v1 >> 32);
        }
        #pragma unroll
        for (int i = 0; i < MT; i++)
            #pragma unroll
            for (int j = 0; j < NTw; j++) {
                mma16816(d[i][j], ah[i], bh[j]);
                mma16816(d[i][j], ah[i], bl[j]);
                mma16816(d[i][j], al[i], bh[j]);
            }

        if (ks == KS - 1) {
            // epilogue for this n-tile
            int nt = s / KS;
            #pragma unroll
            for (int i = 0; i < MT; i++) {
                int row0 = m0 + m0w + 16 * i + gr;
                int row1 = row0 + 8;
                #pragma unroll
                for (int j = 0; j < NTw; j++) {
                    int col = nt * BN + n0w + 8 * j + 2 * thc;
                    float b0 = bias[col], b1 = bias[col + 1];
                    float v00 = d[i][j][0] + b0, v01 = d[i][j][1] + b1;
                    float v10 = d[i][j][2] + b0, v11 = d[i][j][3] + b1;
                    if (RELU) {
                        v00 = fmaxf(v00, 0.0f); v01 = fmaxf(v01, 0.0f);
                        v10 = fmaxf(v10, 0.0f); v11 = fmaxf(v11, 0.0f);
                    }
                    if (OMODE == 0) {
                        if (row0 < M) *(float2*)(outf + (size_t)row0 * ldo_p + col) = make_float2(v00, v01);
                        if (row1 < M) *(float2*)(outf + (size_t)row1 * ldo_p + col) = make_float2(v10, v11);
                    } else if (OMODE == 1) {
                        int pidx = (ocol0 + col) >> 1;
                        if (row0 < M) outs[(size_t)row0 * ldo_p + pidx] = splitpair(v00, v01);
                        if (row1 < M) outs[(size_t)row1 * ldo_p + pidx] = splitpair(v10, v11);
                    } else {
                        float* dst = (col < 256) ? outf : outf2;
                        int cc = (col < 256) ? col : col - 256;
                        if (row0 < M) *(float2*)(dst + (size_t)row0 * 256 + cc) = make_float2(v00, v01);
                        if (row1 < M) *(float2*)(dst + (size_t)row1 * 256 + cc) = make_float2(v10, v11);
                    }
                    d[i][j][0] = d[i][j][1] = d[i][j][2] = d[i][j][3] = 0.0f;
                }
            }
        }
        __syncthreads();
    }
}

// ---------------- fuse GEMM (small, unchanged double-buffer kernel) ----------------
template <int BM, int BN, int WM, int WN, bool RELU>
__global__ __launch_bounds__(256, 3) void mma_gemm_small(
    const u64* __restrict__ As, const u64* __restrict__ Ws,
    const float* __restrict__ bias, float* __restrict__ outf,
    int ldo_p, int M, int K, int Nfull)
{
    constexpr int PC = 8;
    constexpr int SRA = 12;
    constexpr int SRW = BN + 4;
    constexpr int WARPS_N = BN / WN;
    constexpr int MT = WM / 16, NT = WN / 8;
    static_assert((BM / WM) * (BN / WN) == 8, "warp grid must cover block tile");
    constexpr int A_OPS = BM * PC / 2;
    constexpr int W_OPS = PC * BN / 2;
    __shared__ u64 Asm[2][BM][SRA];
    __shared__ u64 Wsm[2][PC][SRW];

    int tid = threadIdx.x;
    int w = tid >> 5, lane = tid & 31;
    int gr = lane >> 2, thc = lane & 3;
    int wm = w / WARPS_N, wn = w % WARPS_N;
    int m0 = blockIdx.y * BM, n0 = blockIdx.x * BN;
    int m0w = wm * WM, n0w = wn * WN;
    int Kp = K >> 1, NS = Kp / PC;

    float d[MT][NT][4] = {};

    auto issue_stage = [&](int buf, int p0) {
        #pragma unroll
        for (int j = 0; j < (A_OPS + 255) / 256; j++) {
            int p = tid + j * 256;
            if ((A_OPS % 256 == 0) || p < A_OPS) {
                int row = p >> 2, dc = (p & 3) * 2;
                u32 sa = (u32)__cvta_generic_to_shared(&Asm[buf][row][dc]);
                cpasync16(sa, As + (size_t)(m0 + row) * Kp + p0 + dc, (m0 + row) < M);
            }
        }
        #pragma unroll
        for (int j = 0; j < (W_OPS + 255) / 256; j++) {
            int p = tid + j * 256;
            if ((W_OPS % 256 == 0) || p < W_OPS) {
                int c = p / (BN / 2), dn = (p % (BN / 2)) * 2;
                u32 sa = (u32)__cvta_generic_to_shared(&Wsm[buf][c][dn]);
                cpasync16(sa, Ws + (size_t)(p0 + c) * Nfull + n0 + dn, true);
            }
        }
        CP_COMMIT();
    };

    issue_stage(0, 0);
    for (int s = 0; s < NS; s++) {
        int buf = s & 1;
        if (s + 1 < NS) issue_stage(buf ^ 1, (s + 1) * PC);
        else CP_COMMIT();
        CP_WAIT1();
        __syncthreads();

        u32 ah[MT][4], al[MT][4], bh[NT][2], bl[NT][2];
        #pragma unroll
        for (int i = 0; i < MT; i++) {
            int r0 = m0w + 16 * i + gr, r1 = r0 + 8;
            u64 v0 = Asm[buf][r0][thc],     v1 = Asm[buf][r1][thc];
            u64 v2 = Asm[buf][r0][thc + 4], v3 = Asm[buf][r1][thc + 4];
            ah[i][0] = (u32)v0; al[i][0] = (u32)(v0 >> 32);
            ah[i][1] = (u32)v1; al[i][1] = (u32)(v1 >> 32);
            ah[i][2] = (u32)v2; al[i][2] = (u32)(v2 >> 32);
            ah[i][3] = (u32)v3; al[i][3] = (u32)(v3 >> 32);
        }
        #pragma unroll
        for (int j = 0; j < NT; j++) {
            int nn = n0w + 8 * j + gr;
            u64 v0 = Wsm[buf][thc][nn], v1 = Wsm[buf][thc + 4][nn];
            bh[j][0] = (u32)v0; bl[j][0] = (u32)(v0 >> 32);
            bh[j][1] = (u32)v1; bl[j][1] = (u32)(v1 >> 32);
        }
        #pragma unroll
        for (int i = 0; i < MT; i++)
            #pragma unroll
            for (int j = 0; j < NT; j++) {
                mma16816(d[i][j], ah[i], bh[j]);
                mma16816(d[i][j], ah[i], bl[j]);
                mma16816(d[i][j], al[i], bh[j]);
            }
        __syncthreads();
    }

    #pragma unroll
    for (int i = 0; i < MT; i++) {
        int row0 = m0 + m0w + 16 * i + gr;
        int row1 = row0 + 8;
        #pragma unroll
        for (int j = 0; j < NT; j++) {
            int col = n0 + n0w + 8 * j + 2 * thc;
            float b0 = bias[col], b1 = bias[col + 1];
            float v00 = d[i][j][0] + b0, v01 = d[i][j][1] + b1;
            float v10 = d[i][j][2] + b0, v11 = d[i][j][3] + b1;
            if (RELU) {
                v00 = fmaxf(v00, 0.0f); v01 = fmaxf(v01, 0.0f);
                v10 = fmaxf(v10, 0.0f); v11 = fmaxf(v11, 0.0f);
            }
            if (row0 < M) *(float2*)(outf + (size_t)row0 * ldo_p + col) = make_float2(v00, v01);
            if (row1 < M) *(float2*)(outf + (size_t)row1 * ldo_p + col) = make_float2(v10, v11);
        }
    }
}

// ---------------- per-dst aggregation ----------------
__global__ void aggregate_kernel(const float* __restrict__ x) {
    int gw = (blockIdx.x * blockDim.x + threadIdx.x) >> 5;
    int lane = threadIdx.x & 31;
    if (gw >= N_NODESC) return;
    int beg = g_off[gw], end = g_off[gw + 1];
    const float4* Ar = (const float4*)(g_Aarr + (size_t)gw * 256);
    float4 a0 = Ar[lane], a1 = Ar[32 + lane];
    float4 na = make_float4(0, 0, 0, 0);
    float4 e0 = na, e1 = na;
    for (int e = beg; e < end; e++) {
        int s = g_csr[e];
        float4 xv = ((const float4*)(x + (size_t)s * 128))[lane];
        const float4* br = (const float4*)(g_Barr + (size_t)s * 256);
        float4 b0 = br[lane], b1 = br[32 + lane];
        na.x += xv.x; na.y += xv.y; na.z += xv.z; na.w += xv.w;
        e0.x += fmaxf(a0.x + b0.x, 0.0f);
        e0.y += fmaxf(a0.y + b0.y, 0.0f);
        e0.z += fmaxf(a0.z + b0.z, 0.0f);
        e0.w += fmaxf(a0.w + b0.w, 0.0f);
        e1.x += fmaxf(a1.x + b1.x, 0.0f);
        e1.y += fmaxf(a1.y + b1.y, 0.0f);
        e1.z += fmaxf(a1.z + b1.z, 0.0f);
        e1.w += fmaxf(a1.w + b1.w, 0.0f);
    }
    u64* nw = g_nas + (size_t)gw * 64;
    nw[2 * lane]     = splitpair(na.x, na.y);
    nw[2 * lane + 1] = splitpair(na.z, na.w);
    u64* ew = g_eas + (size_t)gw * 128;
    ew[2 * lane]          = splitpair(e0.x, e0.y);
    ew[2 * lane + 1]      = splitpair(e0.z, e0.w);
    ew[64 + 2 * lane]     = splitpair(e1.x, e1.y);
    ew[64 + 2 * lane + 1] = splitpair(e1.z, e1.w);
}

// ---------------- final sigmoid ----------------
__global__ void sigmoid_kernel(const float* __restrict__ Wf2, const float* __restrict__ bf2,
                               float* __restrict__ out) {
    int gw = (blockIdx.x * blockDim.x + threadIdx.x) >> 5;
    int lane = threadIdx.x & 31;
    if (gw >= N_NODESC) return;
    float t = g_h2[(size_t)gw * 32 + lane] * Wf2[lane];
    #pragma unroll
    for (int o = 16; o; o >>= 1) t += __shfl_xor_sync(0xffffffffu, t, o);
    if (lane == 0) out[gw] = 1.0f / (1.0f + __expf(-(t + bf2[0])));
}

// ---------------- launch ----------------
extern "C" void kernel_launch(void* const* d_in, const int* in_sizes, int n_in,
                              void* d_out, int out_size) {
    const float* x  = (const float*)d_in[0];
    const void*  ei = d_in[1];
    const float* W_node = (const float*)d_in[3];
    const float* b_node = (const float*)d_in[4];
    const float* W_edge = (const float*)d_in[5];
    const float* b_edge = (const float*)d_in[6];
    const float* W_ed   = (const float*)d_in[7];
    const float* b_ed   = (const float*)d_in[8];
    const float* W_f1   = (const float*)d_in[9];
    const float* b_f1   = (const float*)d_in[10];
    const float* W_f2   = (const float*)d_in[11];
    const float* b_f2   = (const float*)d_in[12];
    float* out = (float*)d_out;

    u64 *pxs, *pnas, *peas, *phs, *pWcs, *pWns, *pWes, *pWfs;
    float *pA, *pB, *pbc, *ph2;
    cudaGetSymbolAddress((void**)&pxs,  g_xs);
    cudaGetSymbolAddress((void**)&pnas, g_nas);
    cudaGetSymbolAddress((void**)&peas, g_eas);
    cudaGetSymbolAddress((void**)&phs,  g_hs);
    cudaGetSymbolAddress((void**)&pWcs, g_Wcs);
    cudaGetSymbolAddress((void**)&pWns, g_Wns);
    cudaGetSymbolAddress((void**)&pWes, g_Wes);
    cudaGetSymbolAddress((void**)&pWfs, g_Wfs);
    cudaGetSymbolAddress((void**)&pA,   g_Aarr);
    cudaGetSymbolAddress((void**)&pB,   g_Barr);
    cudaGetSymbolAddress((void**)&pbc,  g_bc);
    cudaGetSymbolAddress((void**)&ph2,  g_h2);

    const int MB128 = (N_NODESC + 127) / 128;   // 391

    // dynamic smem sizes (u64 elements -> bytes)
    auto kAB   = mma_gemm_ares<128, 64, 32, 128, 512, false, 2>;
    auto kNode = mma_gemm_ares<128, 64, 32, 128, 256, true, 1>;
    auto kEdge = mma_gemm_ares<128, 64, 32, 256, 128, true, 1>;
    const int smAB   = (128 * 68  + 2 * 8 * 132) * 8;   // 86528
    const int smNode = smAB;
    const int smEdge = (128 * 132 + 2 * 8 * 132) * 8;   // 152064
    cudaFuncSetAttribute(kAB,   cudaFuncAttributeMaxDynamicSharedMemorySize, smAB);
    cudaFuncSetAttribute(kNode, cudaFuncAttributeMaxDynamicSharedMemorySize, smNode);
    cudaFuncSetAttribute(kEdge, cudaFuncAttributeMaxDynamicSharedMemorySize, smEdge);

    // Launches 1-3, then AB GEMM as launch #4 (ncu captures the 4th launch)
    zero_init_kernel<<<(N_NODESC + 255) / 256, 256>>>();
    prep_w_kernel<<<128, 256>>>(W_edge, b_edge, W_node, W_ed, W_f1);
    split_x_kernel<<<(N_NODESC * 64 + 255) / 256, 256>>>(x);

    // AB = x @ Wc -> Aarr (bias folded) / Barr, fp32
    kAB<<<MB128, 256, smAB>>>(pxs, pWcs, pbc, pA, (u64*)0, pB, 0, 0, N_NODESC);

    // edge pipeline
    detect_kernel<<<256, 256>>>((const int*)ei);
    conv_hist_kernel<<<(N_EDGESC + 255) / 256, 256>>>(ei);
    scan1_kernel<<<SCAN_BLKS, 1024>>>();
    scan2_kernel<<<1, 64>>>();
    scan3_kernel<<<(N_NODESC + 255) / 256, 256>>>();
    scatter_kernel<<<(N_EDGESC + 255) / 256, 256>>>();

    aggregate_kernel<<<(N_NODESC + 7) / 8, 256>>>(x);

    // nodes -> h[:,0:256) split ; edges -> h[:,256:384) split
    kNode<<<MB128, 256, smNode>>>(pnas, pWns, b_node, (float*)0, phs, (float*)0, 192, 0, N_NODESC);
    kEdge<<<MB128, 256, smEdge>>>(peas, pWes, b_ed, (float*)0, phs, (float*)0, 192, 256, N_NODESC);

    // h2 = relu(h @ W_f1 + b_f1), fp32
    mma_gemm_small<128, 32, 32, 16, true><<<dim3(1, MB128), 256>>>(
        phs, pWfs, b_f1, ph2, 32, N_NODESC, 384, 32);

    sigmoid_kernel<<<(N_NODESC + 7) / 8, 256>>>(W_f2, b_f2, out);
}

// round 10
// speedup vs baseline: 1.1023x; 1.1023x over previous
#include <cuda_runtime.h>
#include <cuda_bf16.h>

#define N_NODESC 50000
#define N_EDGESC 400000
#define SCAN_BLKS 49   // ceil(50000/1024)

typedef unsigned int u32;
typedef unsigned long long u64;

// ---------------- device scratch ----------------
__device__ u64   g_xs[(size_t)N_NODESC * 64];     // x split: [row][pair] (hi|lo packed u64)
__device__ float g_Aarr[(size_t)N_NODESC * 256];  // A-half of edge pre-act (+b_edge)
__device__ float g_Barr[(size_t)N_NODESC * 256];  // B-half (gathered randomly; L2-resident)
__device__ u64   g_nas[(size_t)N_NODESC * 64];    // node_agg split
__device__ u64   g_eas[(size_t)N_NODESC * 128];   // edge_agg split
__device__ u64   g_hs[(size_t)N_NODESC * 192];    // h split
__device__ float g_h2[(size_t)N_NODESC * 32];
__device__ u64   g_Wcs[64 * 512];                 // Wc split  [pair][n]
__device__ u64   g_Wns[64 * 256];
__device__ u64   g_Wes[128 * 128];
__device__ u64   g_Wfs[192 * 32];
__device__ float g_bc[512];
__device__ int   g_count[N_NODESC];
__device__ int   g_off[N_NODESC + 1];
__device__ int   g_cur[N_NODESC];
__device__ int   g_csr[N_EDGESC];
__device__ int   g_ei32[2 * N_EDGESC];
__device__ int   g_bsum[SCAN_BLKS];
__device__ int   g_bpre[SCAN_BLKS];
__device__ int   g_dtype_flag;

// ---------------- helpers ----------------
__device__ __forceinline__ u64 splitpair(float a, float b) {
    __nv_bfloat162 h = __float22bfloat162_rn(make_float2(a, b));
    float2 hf = __bfloat1622float2(h);
    __nv_bfloat162 l = __float22bfloat162_rn(make_float2(a - hf.x, b - hf.y));
    u32 hw = *(u32*)&h, lw = *(u32*)&l;
    return (u64)hw | ((u64)lw << 32);
}

__device__ __forceinline__ void mma16816(float* d, const u32* a, const u32* b) {
    asm volatile(
        "mma.sync.aligned.m16n8k16.row.col.f32.bf16.bf16.f32 "
        "{%0,%1,%2,%3}, {%4,%5,%6,%7}, {%8,%9}, {%0,%1,%2,%3};\n"
        : "+f"(d[0]), "+f"(d[1]), "+f"(d[2]), "+f"(d[3])
        : "r"(a[0]), "r"(a[1]), "r"(a[2]), "r"(a[3]), "r"(b[0]), "r"(b[1]));
}

// 16-byte cp.async (cg = L2 path). pred=false -> zero-fill.
__device__ __forceinline__ void cpasync16(u32 saddr, const void* g, bool pred) {
    int sz = pred ? 16 : 0;
    asm volatile("cp.async.cg.shared.global [%0], [%1], 16, %2;\n"
                 :: "r"(saddr), "l"(g), "r"(sz));
}
#define CP_COMMIT() asm volatile("cp.async.commit_group;\n")
#define CP_WAIT2()  asm volatile("cp.async.wait_group 2;\n")

// ---------------- setup: zero counts + split weights + split x (merged) ----------------
__device__ __forceinline__ float wcval(const float* We, int k, int n) {
    return (n < 256) ? (We[k * 256 + n] - We[(128 + k) * 256 + n])
                     : We[(128 + k) * 256 + (n - 256)];
}

#define SPLITX_BLKS 12500   // N_NODESC*64/256
#define PREPW_BLKS  128
#define ZERO_BLKS   196

__global__ void setup_kernel(const float* __restrict__ x,
                             const float* __restrict__ We, const float* __restrict__ be,
                             const float* __restrict__ Wn, const float* __restrict__ Wd,
                             const float* __restrict__ Wf) {
    int b = blockIdx.x, tid = threadIdx.x;
    if (b < SPLITX_BLKS) {
        int idx = b * 256 + tid;
        int row = idx >> 6, c = idx & 63;
        float2 v = *(const float2*)(x + (size_t)row * 128 + 2 * c);
        g_xs[idx] = splitpair(v.x, v.y);
    } else if (b < SPLITX_BLKS + PREPW_BLKS) {
        int idx = (b - SPLITX_BLKS) * 256 + tid;   // 0..32767
        {
            int c = idx >> 9, n = idx & 511;
            g_Wcs[idx] = splitpair(wcval(We, 2 * c, n), wcval(We, 2 * c + 1, n));
        }
        if (idx < 64 * 256) {
            int c = idx >> 8, n = idx & 255;
            g_Wns[idx] = splitpair(Wn[2 * c * 256 + n], Wn[(2 * c + 1) * 256 + n]);
        }
        if (idx < 128 * 128) {
            int c = idx >> 7, n = idx & 127;
            g_Wes[idx] = splitpair(Wd[2 * c * 128 + n], Wd[(2 * c + 1) * 128 + n]);
        }
        if (idx < 192 * 32) {
            int c = idx >> 5, n = idx & 31;
            g_Wfs[idx] = splitpair(Wf[2 * c * 32 + n], Wf[(2 * c + 1) * 32 + n]);
        }
        if (idx < 512) g_bc[idx] = (idx < 256) ? be[idx] : 0.0f;
    } else {
        int i = (b - SPLITX_BLKS - PREPW_BLKS) * 256 + tid;
        if (i < N_NODESC) g_count[i] = 0;
        if (i == 0) g_dtype_flag = 0;
    }
}

// ---------------- dtype detect / convert+hist ----------------
__global__ void detect_kernel(const int* __restrict__ w) {
    int acc = 0;
    for (int i = blockIdx.x * blockDim.x + threadIdx.x; i < N_EDGESC; i += gridDim.x * blockDim.x)
        acc |= w[2 * i + 1];
    #pragma unroll
    for (int o = 16; o; o >>= 1) acc |= __shfl_xor_sync(0xffffffffu, acc, o);
    if ((threadIdx.x & 31) == 0 && acc) atomicOr(&g_dtype_flag, 1);
}

__global__ void conv_hist_kernel(const void* __restrict__ ei) {
    int e = blockIdx.x * blockDim.x + threadIdx.x;
    if (e < N_EDGESC) {
        int s, d;
        if (g_dtype_flag) {
            s = ((const int*)ei)[e];
            d = ((const int*)ei)[N_EDGESC + e];
        } else {
            s = (int)((const long long*)ei)[e];
            d = (int)((const long long*)ei)[N_EDGESC + e];
        }
        g_ei32[e] = s;
        g_ei32[N_EDGESC + e] = d;
        atomicAdd(&g_count[d], 1);
    }
}

// ---------------- parallel scan ----------------
__global__ void scan1_kernel() {
    __shared__ int wsum[32], wpre[32];
    int tid = threadIdx.x, lane = tid & 31, w = tid >> 5;
    int i = blockIdx.x * 1024 + tid;
    int orig = (i < N_NODESC) ? g_count[i] : 0;
    int v = orig;
    #pragma unroll
    for (int o = 1; o < 32; o <<= 1) {
        int t = __shfl_up_sync(0xffffffffu, v, o);
        if (lane >= o) v += t;
    }
    if (lane == 31) wsum[w] = v;
    __syncthreads();
    if (w == 0) {
        int s = wsum[lane], sv = s;
        #pragma unroll
        for (int o = 1; o < 32; o <<= 1) {
            int t = __shfl_up_sync(0xffffffffu, sv, o);
            if (lane >= o) sv += t;
        }
        wpre[lane] = sv - s;
        if (lane == 31) g_bsum[blockIdx.x] = sv;
    }
    __syncthreads();
    if (i < N_NODESC) {
        int ex = wpre[w] + v - orig;
        g_off[i] = ex;
        g_cur[i] = ex;
    }
}

__global__ void scan2_kernel() {
    __shared__ int s[64];
    int tid = threadIdx.x;
    int orig = (tid < SCAN_BLKS) ? g_bsum[tid] : 0;
    s[tid] = orig;
    __syncthreads();
    #pragma unroll
    for (int o = 1; o < 64; o <<= 1) {
        int t = (tid >= o) ? s[tid - o] : 0;
        __syncthreads();
        s[tid] += t;
        __syncthreads();
    }
    if (tid < SCAN_BLKS) g_bpre[tid] = s[tid] - orig;
    if (tid == 63) g_off[N_NODESC] = s[63];
}

__global__ void scan3_kernel() {
    int i = blockIdx.x * blockDim.x + threadIdx.x;
    if (i < N_NODESC) {
        int add = g_bpre[i >> 10];
        g_off[i] += add;
        g_cur[i] += add;
    }
}

__global__ void scatter_kernel() {
    int e = blockIdx.x * blockDim.x + threadIdx.x;
    if (e < N_EDGESC) {
        int d = g_ei32[N_EDGESC + e];
        int s = g_ei32[e];
        int p = atomicAdd(&g_cur[d], 1);
        g_csr[p] = s;
    }
}

// ---------------- 3-stage cp.async tensor-core GEMM ----------------
// Warp grid: (BM/WM)*(BN/WN) == 8. A smem [row][12 u64]: frag addr
// (gr*12+thc) mod 16 covers 16 bank-pairs. W smem [c][BN+4 u64]: cp.async
// fills contiguous; frag reads (4*thc+gr) mod 16 distinct. Conflict-free.
// 3 buffers + wait_group 2: each stage's loads get 2 compute stages to land.
// OMODE: 0 = fp32 out, 1 = split-u64 out, 2 = AB dual fp32 (Aarr/Barr)
template <int BM, int BN, int WM, int WN, bool RELU, int OMODE>
__global__ __launch_bounds__(256, 3) void mma_gemm(
    const u64* __restrict__ As,      // [M][K/2]
    const u64* __restrict__ Ws,      // [K/2][Nfull]
    const float* __restrict__ bias,
    float* __restrict__ outf, u64* __restrict__ outs, float* __restrict__ outf2,
    int ldo_p, int ocol0, int M, int K, int Nfull)
{
    constexpr int PC = 8;                        // pairs per stage (one k16)
    constexpr int SRA = 12;                      // A row stride (u64)
    constexpr int SRW = BN + 4;                  // W row stride (u64), ≡4 mod 16
    constexpr int WARPS_N = BN / WN;
    constexpr int MT = WM / 16, NT = WN / 8;
    static_assert((BM / WM) * (BN / WN) == 8, "warp grid must cover block tile");
    constexpr int A_OPS = BM * PC / 2;           // 16B ops per A stage
    constexpr int W_OPS = PC * BN / 2;           // 16B ops per W stage
    __shared__ u64 Asm[3][BM][SRA];
    __shared__ u64 Wsm[3][PC][SRW];

    int tid = threadIdx.x;
    int w = tid >> 5, lane = tid & 31;
    int gr = lane >> 2, thc = lane & 3;
    int wm = w / WARPS_N, wn = w % WARPS_N;
    int m0 = blockIdx.y * BM, n0 = blockIdx.x * BN;
    int m0w = wm * WM, n0w = wn * WN;
    int Kp = K >> 1, NS = Kp / PC;

    float d[MT][NT][4] = {};

    auto issue_stage = [&](int buf, int p0) {
        #pragma unroll
        for (int j = 0; j < (A_OPS + 255) / 256; j++) {
            int p = tid + j * 256;
            if ((A_OPS % 256 == 0) || p < A_OPS) {
                int row = p >> 2, dc = (p & 3) * 2;
                u32 sa = (u32)__cvta_generic_to_shared(&Asm[buf][row][dc]);
                cpasync16(sa, As + (size_t)(m0 + row) * Kp + p0 + dc, (m0 + row) < M);
            }
        }
        #pragma unroll
        for (int j = 0; j < (W_OPS + 255) / 256; j++) {
            int p = tid + j * 256;
            if ((W_OPS % 256 == 0) || p < W_OPS) {
                int c = p / (BN / 2), dn = (p % (BN / 2)) * 2;
                u32 sa = (u32)__cvta_generic_to_shared(&Wsm[buf][c][dn]);
                cpasync16(sa, Ws + (size_t)(p0 + c) * Nfull + n0 + dn, true);
            }
        }
        CP_COMMIT();
    };

    issue_stage(0, 0);
    issue_stage(1, PC);
    for (int s = 0; s < NS; s++) {
        int buf = s % 3;
        if (s + 2 < NS) issue_stage((s + 2) % 3, (s + 2) * PC);
        else CP_COMMIT();            // keep group count aligned for wait_group 2
        CP_WAIT2();
        __syncthreads();

        u32 ah[MT][4], al[MT][4], bh[NT][2], bl[NT][2];
        #pragma unroll
        for (int i = 0; i < MT; i++) {
            int r0 = m0w + 16 * i + gr, r1 = r0 + 8;
            u64 v0 = Asm[buf][r0][thc],     v1 = Asm[buf][r1][thc];
            u64 v2 = Asm[buf][r0][thc + 4], v3 = Asm[buf][r1][thc + 4];
            ah[i][0] = (u32)v0; al[i][0] = (u32)(v0 >> 32);
            ah[i][1] = (u32)v1; al[i][1] = (u32)(v1 >> 32);
            ah[i][2] = (u32)v2; al[i][2] = (u32)(v2 >> 32);
            ah[i][3] = (u32)v3; al[i][3] = (u32)(v3 >> 32);
        }
        #pragma unroll
        for (int j = 0; j < NT; j++) {
            int nn = n0w + 8 * j + gr;
            u64 v0 = Wsm[buf][thc][nn], v1 = Wsm[buf][thc + 4][nn];
            bh[j][0] = (u32)v0; bl[j][0] = (u32)(v0 >> 32);
            bh[j][1] = (u32)v1; bl[j][1] = (u32)(v1 >> 32);
        }
        #pragma unroll
        for (int i = 0; i < MT; i++)
            #pragma unroll
            for (int j = 0; j < NT; j++) {
                mma16816(d[i][j], ah[i], bh[j]);
                mma16816(d[i][j], ah[i], bl[j]);
                mma16816(d[i][j], al[i], bh[j]);
            }
        __syncthreads();
    }

    // epilogue
    #pragma unroll
    for (int i = 0; i < MT; i++) {
        int row0 = m0 + m0w + 16 * i + gr;
        int row1 = row0 + 8;
        #pragma unroll
        for (int j = 0; j < NT; j++) {
            int col = n0 + n0w + 8 * j + 2 * thc;
            float b0 = bias[col], b1 = bias[col + 1];
            float v00 = d[i][j][0] + b0, v01 = d[i][j][1] + b1;
            float v10 = d[i][j][2] + b0, v11 = d[i][j][3] + b1;
            if (RELU) {
                v00 = fmaxf(v00, 0.0f); v01 = fmaxf(v01, 0.0f);
                v10 = fmaxf(v10, 0.0f); v11 = fmaxf(v11, 0.0f);
            }
            if (OMODE == 0) {
                if (row0 < M) *(float2*)(outf + (size_t)row0 * ldo_p + col) = make_float2(v00, v01);
                if (row1 < M) *(float2*)(outf + (size_t)row1 * ldo_p + col) = make_float2(v10, v11);
            } else if (OMODE == 1) {
                int pidx = (ocol0 + col) >> 1;
                if (row0 < M) outs[(size_t)row0 * ldo_p + pidx] = splitpair(v00, v01);
                if (row1 < M) outs[(size_t)row1 * ldo_p + pidx] = splitpair(v10, v11);
            } else {
                float* dst = (col < 256) ? outf : outf2;
                int cc = (col < 256) ? col : col - 256;
                if (row0 < M) *(float2*)(dst + (size_t)row0 * 256 + cc) = make_float2(v00, v01);
                if (row1 < M) *(float2*)(dst + (size_t)row1 * 256 + cc) = make_float2(v10, v11);
            }
        }
    }
}

// ---------------- per-dst aggregation ----------------
__global__ void aggregate_kernel(const float* __restrict__ x) {
    int gw = (blockIdx.x * blockDim.x + threadIdx.x) >> 5;
    int lane = threadIdx.x & 31;
    if (gw >= N_NODESC) return;
    int beg = g_off[gw], end = g_off[gw + 1];
    const float4* Ar = (const float4*)(g_Aarr + (size_t)gw * 256);
    float4 a0 = Ar[lane], a1 = Ar[32 + lane];
    float4 na = make_float4(0, 0, 0, 0);
    float4 e0 = na, e1 = na;
    for (int e = beg; e < end; e++) {
        int s = g_csr[e];
        float4 xv = ((const float4*)(x + (size_t)s * 128))[lane];
        const float4* br = (const float4*)(g_Barr + (size_t)s * 256);
        float4 b0 = br[lane], b1 = br[32 + lane];
        na.x += xv.x; na.y += xv.y; na.z += xv.z; na.w += xv.w;
        e0.x += fmaxf(a0.x + b0.x, 0.0f);
        e0.y += fmaxf(a0.y + b0.y, 0.0f);
        e0.z += fmaxf(a0.z + b0.z, 0.0f);
        e0.w += fmaxf(a0.w + b0.w, 0.0f);
        e1.x += fmaxf(a1.x + b1.x, 0.0f);
        e1.y += fmaxf(a1.y + b1.y, 0.0f);
        e1.z += fmaxf(a1.z + b1.z, 0.0f);
        e1.w += fmaxf(a1.w + b1.w, 0.0f);
    }
    u64* nw = g_nas + (size_t)gw * 64;
    nw[2 * lane]     = splitpair(na.x, na.y);
    nw[2 * lane + 1] = splitpair(na.z, na.w);
    u64* ew = g_eas + (size_t)gw * 128;
    ew[2 * lane]          = splitpair(e0.x, e0.y);
    ew[2 * lane + 1]      = splitpair(e0.z, e0.w);
    ew[64 + 2 * lane]     = splitpair(e1.x, e1.y);
    ew[64 + 2 * lane + 1] = splitpair(e1.z, e1.w);
}

// ---------------- final sigmoid ----------------
__global__ void sigmoid_kernel(const float* __restrict__ Wf2, const float* __restrict__ bf2,
                               float* __restrict__ out) {
    int gw = (blockIdx.x * blockDim.x + threadIdx.x) >> 5;
    int lane = threadIdx.x & 31;
    if (gw >= N_NODESC) return;
    float t = g_h2[(size_t)gw * 32 + lane] * Wf2[lane];
    #pragma unroll
    for (int o = 16; o; o >>= 1) t += __shfl_xor_sync(0xffffffffu, t, o);
    if (lane == 0) out[gw] = 1.0f / (1.0f + __expf(-(t + bf2[0])));
}

// ---------------- launch ----------------
extern "C" void kernel_launch(void* const* d_in, const int* in_sizes, int n_in,
                              void* d_out, int out_size) {
    const float* x  = (const float*)d_in[0];
    const void*  ei = d_in[1];
    const float* W_node = (const float*)d_in[3];
    const float* b_node = (const float*)d_in[4];
    const float* W_edge = (const float*)d_in[5];
    const float* b_edge = (const float*)d_in[6];
    const float* W_ed   = (const float*)d_in[7];
    const float* b_ed   = (const float*)d_in[8];
    const float* W_f1   = (const float*)d_in[9];
    const float* b_f1   = (const float*)d_in[10];
    const float* W_f2   = (const float*)d_in[11];
    const float* b_f2   = (const float*)d_in[12];
    float* out = (float*)d_out;

    u64 *pxs, *pnas, *peas, *phs, *pWcs, *pWns, *pWes, *pWfs;
    float *pA, *pB, *pbc, *ph2;
    cudaGetSymbolAddress((void**)&pxs,  g_xs);
    cudaGetSymbolAddress((void**)&pnas, g_nas);
    cudaGetSymbolAddress((void**)&peas, g_eas);
    cudaGetSymbolAddress((void**)&phs,  g_hs);
    cudaGetSymbolAddress((void**)&pWcs, g_Wcs);
    cudaGetSymbolAddress((void**)&pWns, g_Wns);
    cudaGetSymbolAddress((void**)&pWes, g_Wes);
    cudaGetSymbolAddress((void**)&pWfs, g_Wfs);
    cudaGetSymbolAddress((void**)&pA,   g_Aarr);
    cudaGetSymbolAddress((void**)&pB,   g_Barr);
    cudaGetSymbolAddress((void**)&pbc,  g_bc);
    cudaGetSymbolAddress((void**)&ph2,  g_h2);

    const int MB64  = (N_NODESC + 63) / 64;     // 782
    const int MB128 = (N_NODESC + 127) / 128;   // 391

    // #1 setup (split x, split weights, zero counts), #2 detect, #3 conv+hist,
    // #4 AB GEMM (ncu captures the 4th launch)
    setup_kernel<<<SPLITX_BLKS + PREPW_BLKS + ZERO_BLKS, 256>>>(
        x, W_edge, b_edge, W_node, W_ed, W_f1);
    detect_kernel<<<256, 256>>>((const int*)ei);
    conv_hist_kernel<<<(N_EDGESC + 255) / 256, 256>>>(ei);

    // AB = x @ Wc -> Aarr (bias folded) / Barr, fp32
    mma_gemm<64, 128, 32, 32, false, 2><<<dim3(4, MB64), 256>>>(
        pxs, pWcs, pbc, pA, (u64*)0, pB, 0, 0, N_NODESC, 128, 512);

    // CSR build
    scan1_kernel<<<SCAN_BLKS, 1024>>>();
    scan2_kernel<<<1, 64>>>();
    scan3_kernel<<<(N_NODESC + 255) / 256, 256>>>();
    scatter_kernel<<<(N_EDGESC + 255) / 256, 256>>>();

    aggregate_kernel<<<(N_NODESC + 7) / 8, 256>>>(x);

    // nodes -> h[:,0:256) split ; edges -> h[:,256:384) split
    mma_gemm<64, 128, 32, 32, true, 1><<<dim3(2, MB64), 256>>>(
        pnas, pWns, b_node, (float*)0, phs, (float*)0, 192, 0, N_NODESC, 128, 256);
    mma_gemm<64, 128, 32, 32, true, 1><<<dim3(1, MB64), 256>>>(
        peas, pWes, b_ed, (float*)0, phs, (float*)0, 192, 256, N_NODESC, 256, 128);

    // h2 = relu(h @ W_f1 + b_f1), fp32
    mma_gemm<128, 32, 32, 16, true, 0><<<dim3(1, MB128), 256>>>(
        phs, pWfs, b_f1, ph2, (u64*)0, (float*)0, 32, 0, N_NODESC, 384, 32);

    sigmoid_kernel<<<(N_NODESC + 7) / 8, 256>>>(W_f2, b_f2, out);
}

// round 12
// speedup vs baseline: 1.1671x; 1.0588x over previous
#include <cuda_runtime.h>
#include <cuda_bf16.h>

#define N_NODESC 50000
#define N_EDGESC 400000
#define SCAN_BLKS 49   // ceil(50000/1024)

typedef unsigned int u32;
typedef unsigned long long u64;

// ---------------- device scratch ----------------
__device__ u64   g_xs[(size_t)N_NODESC * 64];     // x split: [row][pair] (hi|lo packed u64)
__device__ float g_Aarr[(size_t)N_NODESC * 256];  // A-half of edge pre-act (+b_edge)
__device__ float g_Barr[(size_t)N_NODESC * 256];  // B-half (gathered randomly; L2-resident)
__device__ u64   g_nas[(size_t)N_NODESC * 64];    // node_agg split
__device__ u64   g_eas[(size_t)N_NODESC * 128];   // edge_agg split
__device__ u64   g_hs[(size_t)N_NODESC * 192];    // h split
__device__ float g_h2[(size_t)N_NODESC * 32];
__device__ u64   g_Wcs[64 * 512];                 // Wc split  [pair][n]
__device__ u64   g_Wns[64 * 256];
__device__ u64   g_Wes[128 * 128];
__device__ u64   g_Wfs[192 * 32];
__device__ float g_bc[512];
__device__ int   g_count[N_NODESC];
__device__ int   g_off[N_NODESC + 1];
__device__ int   g_cur[N_NODESC];
__device__ int   g_csr[N_EDGESC];
__device__ int   g_ei32[2 * N_EDGESC];
__device__ int   g_bsum[SCAN_BLKS];
__device__ int   g_bpre[SCAN_BLKS];
__device__ int   g_dtype_flag;

// ---------------- helpers ----------------
__device__ __forceinline__ u64 splitpair(float a, float b) {
    __nv_bfloat162 h = __float22bfloat162_rn(make_float2(a, b));
    float2 hf = __bfloat1622float2(h);
    __nv_bfloat162 l = __float22bfloat162_rn(make_float2(a - hf.x, b - hf.y));
    u32 hw = *(u32*)&h, lw = *(u32*)&l;
    return (u64)hw | ((u64)lw << 32);
}

__device__ __forceinline__ void mma16816(float* d, const u32* a, const u32* b) {
    asm volatile(
        "mma.sync.aligned.m16n8k16.row.col.f32.bf16.bf16.f32 "
        "{%0,%1,%2,%3}, {%4,%5,%6,%7}, {%8,%9}, {%0,%1,%2,%3};\n"
        : "+f"(d[0]), "+f"(d[1]), "+f"(d[2]), "+f"(d[3])
        : "r"(a[0]), "r"(a[1]), "r"(a[2]), "r"(a[3]), "r"(b[0]), "r"(b[1]));
}

// 16-byte cp.async (cg = L2 path). pred=false -> zero-fill.
__device__ __forceinline__ void cpasync16(u32 saddr, const void* g, bool pred) {
    int sz = pred ? 16 : 0;
    asm volatile("cp.async.cg.shared.global [%0], [%1], 16, %2;\n"
                 :: "r"(saddr), "l"(g), "r"(sz));
}
#define CP_COMMIT() asm volatile("cp.async.commit_group;\n")
#define CP_WAIT1()  asm volatile("cp.async.wait_group 1;\n")

// ---------------- zero init (tiny; gate for the CSR branch) ----------------
__global__ void zero_kernel() {
    int i = blockIdx.x * blockDim.x + threadIdx.x;
    if (i < N_NODESC) g_count[i] = 0;
    if (i == 0) g_dtype_flag = 0;
}

// ---------------- split weights + split x ----------------
__device__ __forceinline__ float wcval(const float* We, int k, int n) {
    return (n < 256) ? (We[k * 256 + n] - We[(128 + k) * 256 + n])
                     : We[(128 + k) * 256 + (n - 256)];
}

#define SPLITX_BLKS 12500   // N_NODESC*64/256
#define PREPW_BLKS  128

__global__ void setup_kernel(const float* __restrict__ x,
                             const float* __restrict__ We, const float* __restrict__ be,
                             const float* __restrict__ Wn, const float* __restrict__ Wd,
                             const float* __restrict__ Wf) {
    int b = blockIdx.x, tid = threadIdx.x;
    if (b < SPLITX_BLKS) {
        int idx = b * 256 + tid;
        int row = idx >> 6, c = idx & 63;
        float2 v = *(const float2*)(x + (size_t)row * 128 + 2 * c);
        g_xs[idx] = splitpair(v.x, v.y);
    } else {
        int idx = (b - SPLITX_BLKS) * 256 + tid;   // 0..32767
        {
            int c = idx >> 9, n = idx & 511;
            g_Wcs[idx] = splitpair(wcval(We, 2 * c, n), wcval(We, 2 * c + 1, n));
        }
        if (idx < 64 * 256) {
            int c = idx >> 8, n = idx & 255;
            g_Wns[idx] = splitpair(Wn[2 * c * 256 + n], Wn[(2 * c + 1) * 256 + n]);
        }
        if (idx < 128 * 128) {
            int c = idx >> 7, n = idx & 127;
            g_Wes[idx] = splitpair(Wd[2 * c * 128 + n], Wd[(2 * c + 1) * 128 + n]);
        }
        if (idx < 192 * 32) {
            int c = idx >> 5, n = idx & 31;
            g_Wfs[idx] = splitpair(Wf[2 * c * 32 + n], Wf[(2 * c + 1) * 32 + n]);
        }
        if (idx < 512) g_bc[idx] = (idx < 256) ? be[idx] : 0.0f;
    }
}

// ---------------- dtype detect / convert+hist ----------------
__global__ void detect_kernel(const int* __restrict__ w) {
    int acc = 0;
    for (int i = blockIdx.x * blockDim.x + threadIdx.x; i < N_EDGESC; i += gridDim.x * blockDim.x)
        acc |= w[2 * i + 1];
    #pragma unroll
    for (int o = 16; o; o >>= 1) acc |= __shfl_xor_sync(0xffffffffu, acc, o);
    if ((threadIdx.x & 31) == 0 && acc) atomicOr(&g_dtype_flag, 1);
}

__global__ void conv_hist_kernel(const void* __restrict__ ei) {
    int e = blockIdx.x * blockDim.x + threadIdx.x;
    if (e < N_EDGESC) {
        int s, d;
        if (g_dtype_flag) {
            s = ((const int*)ei)[e];
            d = ((const int*)ei)[N_EDGESC + e];
        } else {
            s = (int)((const long long*)ei)[e];
            d = (int)((const long long*)ei)[N_EDGESC + e];
        }
        g_ei32[e] = s;
        g_ei32[N_EDGESC + e] = d;
        atomicAdd(&g_count[d], 1);
    }
}

// ---------------- parallel scan ----------------
__global__ void scan1_kernel() {
    __shared__ int wsum[32], wpre[32];
    int tid = threadIdx.x, lane = tid & 31, w = tid >> 5;
    int i = blockIdx.x * 1024 + tid;
    int orig = (i < N_NODESC) ? g_count[i] : 0;
    int v = orig;
    #pragma unroll
    for (int o = 1; o < 32; o <<= 1) {
        int t = __shfl_up_sync(0xffffffffu, v, o);
        if (lane >= o) v += t;
    }
    if (lane == 31) wsum[w] = v;
    __syncthreads();
    if (w == 0) {
        int s = wsum[lane], sv = s;
        #pragma unroll
        for (int o = 1; o < 32; o <<= 1) {
            int t = __shfl_up_sync(0xffffffffu, sv, o);
            if (lane >= o) sv += t;
        }
        wpre[lane] = sv - s;
        if (lane == 31) g_bsum[blockIdx.x] = sv;
    }
    __syncthreads();
    if (i < N_NODESC) {
        int ex = wpre[w] + v - orig;
        g_off[i] = ex;
        g_cur[i] = ex;
    }
}

__global__ void scan2_kernel() {
    __shared__ int s[64];
    int tid = threadIdx.x;
    int orig = (tid < SCAN_BLKS) ? g_bsum[tid] : 0;
    s[tid] = orig;
    __syncthreads();
    #pragma unroll
    for (int o = 1; o < 64; o <<= 1) {
        int t = (tid >= o) ? s[tid - o] : 0;
        __syncthreads();
        s[tid] += t;
        __syncthreads();
    }
    if (tid < SCAN_BLKS) g_bpre[tid] = s[tid] - orig;
    if (tid == 63) g_off[N_NODESC] = s[63];
}

__global__ void scan3_kernel() {
    int i = blockIdx.x * blockDim.x + threadIdx.x;
    if (i < N_NODESC) {
        int add = g_bpre[i >> 10];
        g_off[i] += add;
        g_cur[i] += add;
    }
}

__global__ void scatter_kernel() {
    int e = blockIdx.x * blockDim.x + threadIdx.x;
    if (e < N_EDGESC) {
        int d = g_ei32[N_EDGESC + e];
        int s = g_ei32[e];
        int p = atomicAdd(&g_cur[d], 1);
        g_csr[p] = s;
    }
}

// ---------------- 2-stage cp.async tensor-core GEMM (R8 proven config) ----------------
// A smem [row][12 u64]: frag addr (gr*12+thc) mod 16 covers 16 bank-pairs.
// W smem [c][BN+4 u64]: cp.async fills contiguous; frag reads conflict-free.
// OMODE: 0 = fp32 out, 1 = split-u64 out, 2 = AB dual fp32 (Aarr/Barr)
template <int BM, int BN, int WM, int WN, bool RELU, int OMODE>
__global__ __launch_bounds__(256, 3) void mma_gemm(
    const u64* __restrict__ As,      // [M][K/2]
    const u64* __restrict__ Ws,      // [K/2][Nfull]
    const float* __restrict__ bias,
    float* __restrict__ outf, u64* __restrict__ outs, float* __restrict__ outf2,
    int ldo_p, int ocol0, int M, int K, int Nfull)
{
    constexpr int PC = 8;
    constexpr int SRA = 12;
    constexpr int SRW = BN + 4;
    constexpr int WARPS_N = BN / WN;
    constexpr int MT = WM / 16, NT = WN / 8;
    static_assert((BM / WM) * (BN / WN) == 8, "warp grid must cover block tile");
    constexpr int A_OPS = BM * PC / 2;
    constexpr int W_OPS = PC * BN / 2;
    __shared__ u64 Asm[2][BM][SRA];
    __shared__ u64 Wsm[2][PC][SRW];

    int tid = threadIdx.x;
    int w = tid >> 5, lane = tid & 31;
    int gr = lane >> 2, thc = lane & 3;
    int wm = w / WARPS_N, wn = w % WARPS_N;
    int m0 = blockIdx.y * BM, n0 = blockIdx.x * BN;
    int m0w = wm * WM, n0w = wn * WN;
    int Kp = K >> 1, NS = Kp / PC;

    float d[MT][NT][4] = {};

    auto issue_stage = [&](int buf, int p0) {
        #pragma unroll
        for (int j = 0; j < (A_OPS + 255) / 256; j++) {
            int p = tid + j * 256;
            if ((A_OPS % 256 == 0) || p < A_OPS) {
                int row = p >> 2, dc = (p & 3) * 2;
                u32 sa = (u32)__cvta_generic_to_shared(&Asm[buf][row][dc]);
                cpasync16(sa, As + (size_t)(m0 + row) * Kp + p0 + dc, (m0 + row) < M);
            }
        }
        #pragma unroll
        for (int j = 0; j < (W_OPS + 255) / 256; j++) {
            int p = tid + j * 256;
            if ((W_OPS % 256 == 0) || p < W_OPS) {
                int c = p / (BN / 2), dn = (p % (BN / 2)) * 2;
                u32 sa = (u32)__cvta_generic_to_shared(&Wsm[buf][c][dn]);
                cpasync16(sa, Ws + (size_t)(p0 + c) * Nfull + n0 + dn, true);
            }
        }
        CP_COMMIT();
    };

    issue_stage(0, 0);
    for (int s = 0; s < NS; s++) {
        int buf = s & 1;
        if (s + 1 < NS) issue_stage(buf ^ 1, (s + 1) * PC);
        else CP_COMMIT();
        CP_WAIT1();
        __syncthreads();

        u32 ah[MT][4], al[MT][4], bh[NT][2], bl[NT][2];
        #pragma unroll
        for (int i = 0; i < MT; i++) {
            int r0 = m0w + 16 * i + gr, r1 = r0 + 8;
            u64 v0 = Asm[buf][r0][thc],     v1 = Asm[buf][r1][thc];
            u64 v2 = Asm[buf][r0][thc + 4], v3 = Asm[buf][r1][thc + 4];
            ah[i][0] = (u32)v0; al[i][0] = (u32)(v0 >> 32);
            ah[i][1] = (u32)v1; al[i][1] = (u32)(v1 >> 32);
            ah[i][2] = (u32)v2; al[i][2] = (u32)(v2 >> 32);
            ah[i][3] = (u32)v3; al[i][3] = (u32)(v3 >> 32);
        }
        #pragma unroll
        for (int j = 0; j < NT; j++) {
            int nn = n0w + 8 * j + gr;
            u64 v0 = Wsm[buf][thc][nn], v1 = Wsm[buf][thc + 4][nn];
            bh[j][0] = (u32)v0; bl[j][0] = (u32)(v0 >> 32);
            bh[j][1] = (u32)v1; bl[j][1] = (u32)(v1 >> 32);
        }
        #pragma unroll
        for (int i = 0; i < MT; i++)
            #pragma unroll
            for (int j = 0; j < NT; j++) {
                mma16816(d[i][j], ah[i], bh[j]);
                mma16816(d[i][j], ah[i], bl[j]);
                mma16816(d[i][j], al[i], bh[j]);
            }
        __syncthreads();
    }

    #pragma unroll
    for (int i = 0; i < MT; i++) {
        int row0 = m0 + m0w + 16 * i + gr;
        int row1 = row0 + 8;
        #pragma unroll
        for (int j = 0; j < NT; j++) {
            int col = n0 + n0w + 8 * j + 2 * thc;
            float b0 = bias[col], b1 = bias[col + 1];
            float v00 = d[i][j][0] + b0, v01 = d[i][j][1] + b1;
            float v10 = d[i][j][2] + b0, v11 = d[i][j][3] + b1;
            if (RELU) {
                v00 = fmaxf(v00, 0.0f); v01 = fmaxf(v01, 0.0f);
                v10 = fmaxf(v10, 0.0f); v11 = fmaxf(v11, 0.0f);
            }
            if (OMODE == 0) {
                if (row0 < M) *(float2*)(outf + (size_t)row0 * ldo_p + col) = make_float2(v00, v01);
                if (row1 < M) *(float2*)(outf + (size_t)row1 * ldo_p + col) = make_float2(v10, v11);
            } else if (OMODE == 1) {
                int pidx = (ocol0 + col) >> 1;
                if (row0 < M) outs[(size_t)row0 * ldo_p + pidx] = splitpair(v00, v01);
                if (row1 < M) outs[(size_t)row1 * ldo_p + pidx] = splitpair(v10, v11);
            } else {
                float* dst = (col < 256) ? outf : outf2;
                int cc = (col < 256) ? col : col - 256;
                if (row0 < M) *(float2*)(dst + (size_t)row0 * 256 + cc) = make_float2(v00, v01);
                if (row1 < M) *(float2*)(dst + (size_t)row1 * 256 + cc) = make_float2(v10, v11);
            }
        }
    }
}

// ---------------- per-dst aggregation ----------------
__global__ void aggregate_kernel(const float* __restrict__ x) {
    int gw = (blockIdx.x * blockDim.x + threadIdx.x) >> 5;
    int lane = threadIdx.x & 31;
    if (gw >= N_NODESC) return;
    int beg = g_off[gw], end = g_off[gw + 1];
    const float4* Ar = (const float4*)(g_Aarr + (size_t)gw * 256);
    float4 a0 = Ar[lane], a1 = Ar[32 + lane];
    float4 na = make_float4(0, 0, 0, 0);
    float4 e0 = na, e1 = na;
    for (int e = beg; e < end; e++) {
        int s = g_csr[e];
        float4 xv = ((const float4*)(x + (size_t)s * 128))[lane];
        const float4* br = (const float4*)(g_Barr + (size_t)s * 256);
        float4 b0 = br[lane], b1 = br[32 + lane];
        na.x += xv.x; na.y += xv.y; na.z += xv.z; na.w += xv.w;
        e0.x += fmaxf(a0.x + b0.x, 0.0f);
        e0.y += fmaxf(a0.y + b0.y, 0.0f);
        e0.z += fmaxf(a0.z + b0.z, 0.0f);
        e0.w += fmaxf(a0.w + b0.w, 0.0f);
        e1.x += fmaxf(a1.x + b1.x, 0.0f);
        e1.y += fmaxf(a1.y + b1.y, 0.0f);
        e1.z += fmaxf(a1.z + b1.z, 0.0f);
        e1.w += fmaxf(a1.w + b1.w, 0.0f);
    }
    u64* nw = g_nas + (size_t)gw * 64;
    nw[2 * lane]     = splitpair(na.x, na.y);
    nw[2 * lane + 1] = splitpair(na.z, na.w);
    u64* ew = g_eas + (size_t)gw * 128;
    ew[2 * lane]          = splitpair(e0.x, e0.y);
    ew[2 * lane + 1]      = splitpair(e0.z, e0.w);
    ew[64 + 2 * lane]     = splitpair(e1.x, e1.y);
    ew[64 + 2 * lane + 1] = splitpair(e1.z, e1.w);
}

// ---------------- final sigmoid ----------------
__global__ void sigmoid_kernel(const float* __restrict__ Wf2, const float* __restrict__ bf2,
                               float* __restrict__ out) {
    int gw = (blockIdx.x * blockDim.x + threadIdx.x) >> 5;
    int lane = threadIdx.x & 31;
    if (gw >= N_NODESC) return;
    float t = g_h2[(size_t)gw * 32 + lane] * Wf2[lane];
    #pragma unroll
    for (int o = 16; o; o >>= 1) t += __shfl_xor_sync(0xffffffffu, t, o);
    if (lane == 0) out[gw] = 1.0f / (1.0f + __expf(-(t + bf2[0])));
}

// ---------------- launch (fork-join streams; graph-capture-legal) ----------------
extern "C" void kernel_launch(void* const* d_in, const int* in_sizes, int n_in,
                              void* d_out, int out_size) {
    const float* x  = (const float*)d_in[0];
    const void*  ei = d_in[1];
    const float* W_node = (const float*)d_in[3];
    const float* b_node = (const float*)d_in[4];
    const float* W_edge = (const float*)d_in[5];
    const float* b_edge = (const float*)d_in[6];
    const float* W_ed   = (const float*)d_in[7];
    const float* b_ed   = (const float*)d_in[8];
    const float* W_f1   = (const float*)d_in[9];
    const float* b_f1   = (const float*)d_in[10];
    const float* W_f2   = (const float*)d_in[11];
    const float* b_f2   = (const float*)d_in[12];
    float* out = (float*)d_out;

    u64 *pxs, *pnas, *peas, *phs, *pWcs, *pWns, *pWes, *pWfs;
    float *pA, *pB, *pbc, *ph2;
    cudaGetSymbolAddress((void**)&pxs,  g_xs);
    cudaGetSymbolAddress((void**)&pnas, g_nas);
    cudaGetSymbolAddress((void**)&peas, g_eas);
    cudaGetSymbolAddress((void**)&phs,  g_hs);
    cudaGetSymbolAddress((void**)&pWcs, g_Wcs);
    cudaGetSymbolAddress((void**)&pWns, g_Wns);
    cudaGetSymbolAddress((void**)&pWes, g_Wes);
    cudaGetSymbolAddress((void**)&pWfs, g_Wfs);
    cudaGetSymbolAddress((void**)&pA,   g_Aarr);
    cudaGetSymbolAddress((void**)&pB,   g_Barr);
    cudaGetSymbolAddress((void**)&pbc,  g_bc);
    cudaGetSymbolAddress((void**)&ph2,  g_h2);

    const int MB64  = (N_NODESC + 63) / 64;     // 782
    const int MB128 = (N_NODESC + 127) / 128;   // 391

    // One-time host-side resources (no device memory involved).
    static cudaStream_t s_aux = 0;
    static cudaEvent_t ev_zero = 0, ev_csr = 0;
    if (!s_aux) {
        cudaStreamCreateWithFlags(&s_aux, cudaStreamNonBlocking);
        cudaEventCreateWithFlags(&ev_zero, cudaEventDisableTiming);
        cudaEventCreateWithFlags(&ev_csr, cudaEventDisableTiming);
    }

    // main: zero -> fork
    zero_kernel<<<(N_NODESC + 255) / 256, 256>>>();
    cudaEventRecord(ev_zero, 0);
    cudaStreamWaitEvent(s_aux, ev_zero, 0);

    // aux branch: CSR pipeline (independent of splits / AB GEMM)
    detect_kernel<<<256, 256, 0, s_aux>>>((const int*)ei);
    conv_hist_kernel<<<(N_EDGESC + 255) / 256, 256, 0, s_aux>>>(ei);
    scan1_kernel<<<SCAN_BLKS, 1024, 0, s_aux>>>();
    scan2_kernel<<<1, 64, 0, s_aux>>>();
    scan3_kernel<<<(N_NODESC + 255) / 256, 256, 0, s_aux>>>();
    scatter_kernel<<<(N_EDGESC + 255) / 256, 256, 0, s_aux>>>();
    cudaEventRecord(ev_csr, s_aux);

    // main branch (overlaps aux): splits + AB GEMM
    setup_kernel<<<SPLITX_BLKS + PREPW_BLKS, 256>>>(x, W_edge, b_edge, W_node, W_ed, W_f1);
    mma_gemm<64, 128, 32, 32, false, 2><<<dim3(4, MB64), 256>>>(
        pxs, pWcs, pbc, pA, (u64*)0, pB, 0, 0, N_NODESC, 128, 512);

    // join: aggregate needs AB output + CSR
    cudaStreamWaitEvent(0, ev_csr, 0);
    aggregate_kernel<<<(N_NODESC + 7) / 8, 256>>>(x);

    // nodes -> h[:,0:256) split ; edges -> h[:,256:384) split
    mma_gemm<64, 128, 32, 32, true, 1><<<dim3(2, MB64), 256>>>(
        pnas, pWns, b_node, (float*)0, phs, (float*)0, 192, 0, N_NODESC, 128, 256);
    mma_gemm<64, 128, 32, 32, true, 1><<<dim3(1, MB64), 256>>>(
        peas, pWes, b_ed, (float*)0, phs, (float*)0, 192, 256, N_NODESC, 256, 128);

    // h2 = relu(h @ W_f1 + b_f1), fp32
    mma_gemm<128, 32, 32, 16, true, 0><<<dim3(1, MB128), 256>>>(
        phs, pWfs, b_f1, ph2, (u64*)0, (float*)0, 32, 0, N_NODESC, 384, 32);

    sigmoid_kernel<<<(N_NODESC + 7) / 8, 256>>>(W_f2, b_f2, out);
}

// round 13
// speedup vs baseline: 1.2386x; 1.0613x over previous
#include <cuda_runtime.h>
#include <cuda_bf16.h>

#define N_NODESC 50000
#define N_EDGESC 400000
#define SCAN_BLKS 49   // ceil(50000/1024)

typedef unsigned int u32;
typedef unsigned long long u64;

// ---------------- device scratch ----------------
__device__ u64   g_xs[(size_t)N_NODESC * 64];     // x split: [row][pair] (hi|lo packed u64)
__device__ float g_Aarr[(size_t)N_NODESC * 256];  // A-half of edge pre-act (+b_edge)
__device__ float g_Barr[(size_t)N_NODESC * 256];  // B-half (gathered randomly; L2-resident)
__device__ u64   g_nas[(size_t)N_NODESC * 64];    // node_agg split
__device__ u64   g_eas[(size_t)N_NODESC * 128];   // edge_agg split
__device__ u64   g_hs[(size_t)N_NODESC * 192];    // h split
__device__ float g_h2[(size_t)N_NODESC * 32];
__device__ u64   g_Wcs[64 * 512];                 // Wc split  [pair][n]
__device__ u64   g_Wns[64 * 256];
__device__ u64   g_Wes[128 * 128];
__device__ u64   g_Wfs[192 * 32];
__device__ float g_bc[512];
__device__ int   g_count[N_NODESC];
__device__ int   g_off[N_NODESC + 1];
__device__ int   g_cur[N_NODESC];
__device__ int   g_csr[N_EDGESC];
__device__ int   g_ei32[2 * N_EDGESC];
__device__ int   g_bsum[SCAN_BLKS];
__device__ int   g_bpre[SCAN_BLKS];
__device__ int   g_dtype_flag;

// ---------------- helpers ----------------
__device__ __forceinline__ u64 splitpair(float a, float b) {
    __nv_bfloat162 h = __float22bfloat162_rn(make_float2(a, b));
    float2 hf = __bfloat1622float2(h);
    __nv_bfloat162 l = __float22bfloat162_rn(make_float2(a - hf.x, b - hf.y));
    u32 hw = *(u32*)&h, lw = *(u32*)&l;
    return (u64)hw | ((u64)lw << 32);
}

__device__ __forceinline__ void mma16816(float* d, const u32* a, const u32* b) {
    asm volatile(
        "mma.sync.aligned.m16n8k16.row.col.f32.bf16.bf16.f32 "
        "{%0,%1,%2,%3}, {%4,%5,%6,%7}, {%8,%9}, {%0,%1,%2,%3};\n"
        : "+f"(d[0]), "+f"(d[1]), "+f"(d[2]), "+f"(d[3])
        : "r"(a[0]), "r"(a[1]), "r"(a[2]), "r"(a[3]), "r"(b[0]), "r"(b[1]));
}

// 16-byte cp.async (cg = L2 path). pred=false -> zero-fill.
__device__ __forceinline__ void cpasync16(u32 saddr, const void* g, bool pred) {
    int sz = pred ? 16 : 0;
    asm volatile("cp.async.cg.shared.global [%0], [%1], 16, %2;\n"
                 :: "r"(saddr), "l"(g), "r"(sz));
}
#define CP_COMMIT() asm volatile("cp.async.commit_group;\n")
#define CP_WAIT1()  asm volatile("cp.async.wait_group 1;\n")

// ---------------- zero init (tiny; gate for the CSR branch) ----------------
__global__ void zero_kernel() {
    int i = blockIdx.x * blockDim.x + threadIdx.x;
    if (i < N_NODESC) g_count[i] = 0;
    if (i == 0) g_dtype_flag = 0;
}

// ---------------- split weights + split x ----------------
__device__ __forceinline__ float wcval(const float* We, int k, int n) {
    return (n < 256) ? (We[k * 256 + n] - We[(128 + k) * 256 + n])
                     : We[(128 + k) * 256 + (n - 256)];
}

#define SPLITX_BLKS 12500   // N_NODESC*64/256
#define PREPW_BLKS  128

__global__ void setup_kernel(const float* __restrict__ x,
                             const float* __restrict__ We, const float* __restrict__ be,
                             const float* __restrict__ Wn, const float* __restrict__ Wd,
                             const float* __restrict__ Wf) {
    int b = blockIdx.x, tid = threadIdx.x;
    if (b < SPLITX_BLKS) {
        int idx = b * 256 + tid;
        int row = idx >> 6, c = idx & 63;
        float2 v = *(const float2*)(x + (size_t)row * 128 + 2 * c);
        g_xs[idx] = splitpair(v.x, v.y);
    } else {
        int idx = (b - SPLITX_BLKS) * 256 + tid;   // 0..32767
        {
            int c = idx >> 9, n = idx & 511;
            g_Wcs[idx] = splitpair(wcval(We, 2 * c, n), wcval(We, 2 * c + 1, n));
        }
        if (idx < 64 * 256) {
            int c = idx >> 8, n = idx & 255;
            g_Wns[idx] = splitpair(Wn[2 * c * 256 + n], Wn[(2 * c + 1) * 256 + n]);
        }
        if (idx < 128 * 128) {
            int c = idx >> 7, n = idx & 127;
            g_Wes[idx] = splitpair(Wd[2 * c * 128 + n], Wd[(2 * c + 1) * 128 + n]);
        }
        if (idx < 192 * 32) {
            int c = idx >> 5, n = idx & 31;
            g_Wfs[idx] = splitpair(Wf[2 * c * 32 + n], Wf[(2 * c + 1) * 32 + n]);
        }
        if (idx < 512) g_bc[idx] = (idx < 256) ? be[idx] : 0.0f;
    }
}

// ---------------- dtype detect / convert+hist ----------------
__global__ void detect_kernel(const int* __restrict__ w) {
    int acc = 0;
    for (int i = blockIdx.x * blockDim.x + threadIdx.x; i < N_EDGESC; i += gridDim.x * blockDim.x)
        acc |= w[2 * i + 1];
    #pragma unroll
    for (int o = 16; o; o >>= 1) acc |= __shfl_xor_sync(0xffffffffu, acc, o);
    if ((threadIdx.x & 31) == 0 && acc) atomicOr(&g_dtype_flag, 1);
}

__global__ void conv_hist_kernel(const void* __restrict__ ei) {
    int e = blockIdx.x * blockDim.x + threadIdx.x;
    if (e < N_EDGESC) {
        int s, d;
        if (g_dtype_flag) {
            s = ((const int*)ei)[e];
            d = ((const int*)ei)[N_EDGESC + e];
        } else {
            s = (int)((const long long*)ei)[e];
            d = (int)((const long long*)ei)[N_EDGESC + e];
        }
        g_ei32[e] = s;
        g_ei32[N_EDGESC + e] = d;
        atomicAdd(&g_count[d], 1);
    }
}

// ---------------- parallel scan ----------------
__global__ void scan1_kernel() {
    __shared__ int wsum[32], wpre[32];
    int tid = threadIdx.x, lane = tid & 31, w = tid >> 5;
    int i = blockIdx.x * 1024 + tid;
    int orig = (i < N_NODESC) ? g_count[i] : 0;
    int v = orig;
    #pragma unroll
    for (int o = 1; o < 32; o <<= 1) {
        int t = __shfl_up_sync(0xffffffffu, v, o);
        if (lane >= o) v += t;
    }
    if (lane == 31) wsum[w] = v;
    __syncthreads();
    if (w == 0) {
        int s = wsum[lane], sv = s;
        #pragma unroll
        for (int o = 1; o < 32; o <<= 1) {
            int t = __shfl_up_sync(0xffffffffu, sv, o);
            if (lane >= o) sv += t;
        }
        wpre[lane] = sv - s;
        if (lane == 31) g_bsum[blockIdx.x] = sv;
    }
    __syncthreads();
    if (i < N_NODESC) {
        int ex = wpre[w] + v - orig;
        g_off[i] = ex;
        g_cur[i] = ex;
    }
}

__global__ void scan2_kernel() {
    __shared__ int s[64];
    int tid = threadIdx.x;
    int orig = (tid < SCAN_BLKS) ? g_bsum[tid] : 0;
    s[tid] = orig;
    __syncthreads();
    #pragma unroll
    for (int o = 1; o < 64; o <<= 1) {
        int t = (tid >= o) ? s[tid - o] : 0;
        __syncthreads();
        s[tid] += t;
        __syncthreads();
    }
    if (tid < SCAN_BLKS) g_bpre[tid] = s[tid] - orig;
    if (tid == 63) g_off[N_NODESC] = s[63];
}

__global__ void scan3_kernel() {
    int i = blockIdx.x * blockDim.x + threadIdx.x;
    if (i < N_NODESC) {
        int add = g_bpre[i >> 10];
        g_off[i] += add;
        g_cur[i] += add;
    }
}

__global__ void scatter_kernel() {
    int e = blockIdx.x * blockDim.x + threadIdx.x;
    if (e < N_EDGESC) {
        int d = g_ei32[N_EDGESC + e];
        int s = g_ei32[e];
        int p = atomicAdd(&g_cur[d], 1);
        g_csr[p] = s;
    }
}

// ---------------- 2-stage cp.async tensor-core GEMM (proven config) ----------------
// OMODE: 0 = fp32 out, 1 = split-u64 out, 2 = AB dual fp32 (Aarr/Barr)
template <int BM, int BN, int WM, int WN, bool RELU, int OMODE>
__global__ __launch_bounds__(256, 3) void mma_gemm(
    const u64* __restrict__ As,      // [M][K/2]
    const u64* __restrict__ Ws,      // [K/2][Nfull]
    const float* __restrict__ bias,
    float* __restrict__ outf, u64* __restrict__ outs, float* __restrict__ outf2,
    int ldo_p, int ocol0, int M, int K, int Nfull)
{
    constexpr int PC = 8;
    constexpr int SRA = 12;
    constexpr int SRW = BN + 4;
    constexpr int WARPS_N = BN / WN;
    constexpr int MT = WM / 16, NT = WN / 8;
    static_assert((BM / WM) * (BN / WN) == 8, "warp grid must cover block tile");
    constexpr int A_OPS = BM * PC / 2;
    constexpr int W_OPS = PC * BN / 2;
    __shared__ u64 Asm[2][BM][SRA];
    __shared__ u64 Wsm[2][PC][SRW];

    int tid = threadIdx.x;
    int w = tid >> 5, lane = tid & 31;
    int gr = lane >> 2, thc = lane & 3;
    int wm = w / WARPS_N, wn = w % WARPS_N;
    int m0 = blockIdx.y * BM, n0 = blockIdx.x * BN;
    int m0w = wm * WM, n0w = wn * WN;
    int Kp = K >> 1, NS = Kp / PC;

    float d[MT][NT][4] = {};

    auto issue_stage = [&](int buf, int p0) {
        #pragma unroll
        for (int j = 0; j < (A_OPS + 255) / 256; j++) {
            int p = tid + j * 256;
            if ((A_OPS % 256 == 0) || p < A_OPS) {
                int row = p >> 2, dc = (p & 3) * 2;
                u32 sa = (u32)__cvta_generic_to_shared(&Asm[buf][row][dc]);
                cpasync16(sa, As + (size_t)(m0 + row) * Kp + p0 + dc, (m0 + row) < M);
            }
        }
        #pragma unroll
        for (int j = 0; j < (W_OPS + 255) / 256; j++) {
            int p = tid + j * 256;
            if ((W_OPS % 256 == 0) || p < W_OPS) {
                int c = p / (BN / 2), dn = (p % (BN / 2)) * 2;
                u32 sa = (u32)__cvta_generic_to_shared(&Wsm[buf][c][dn]);
                cpasync16(sa, Ws + (size_t)(p0 + c) * Nfull + n0 + dn, true);
            }
        }
        CP_COMMIT();
    };

    issue_stage(0, 0);
    for (int s = 0; s < NS; s++) {
        int buf = s & 1;
        if (s + 1 < NS) issue_stage(buf ^ 1, (s + 1) * PC);
        else CP_COMMIT();
        CP_WAIT1();
        __syncthreads();

        u32 ah[MT][4], al[MT][4], bh[NT][2], bl[NT][2];
        #pragma unroll
        for (int i = 0; i < MT; i++) {
            int r0 = m0w + 16 * i + gr, r1 = r0 + 8;
            u64 v0 = Asm[buf][r0][thc],     v1 = Asm[buf][r1][thc];
            u64 v2 = Asm[buf][r0][thc + 4], v3 = Asm[buf][r1][thc + 4];
            ah[i][0] = (u32)v0; al[i][0] = (u32)(v0 >> 32);
            ah[i][1] = (u32)v1; al[i][1] = (u32)(v1 >> 32);
            ah[i][2] = (u32)v2; al[i][2] = (u32)(v2 >> 32);
            ah[i][3] = (u32)v3; al[i][3] = (u32)(v3 >> 32);
        }
        #pragma unroll
        for (int j = 0; j < NT; j++) {
            int nn = n0w + 8 * j + gr;
            u64 v0 = Wsm[buf][thc][nn], v1 = Wsm[buf][thc + 4][nn];
            bh[j][0] = (u32)v0; bl[j][0] = (u32)(v0 >> 32);
            bh[j][1] = (u32)v1; bl[j][1] = (u32)(v1 >> 32);
        }
        #pragma unroll
        for (int i = 0; i < MT; i++)
            #pragma unroll
            for (int j = 0; j < NT; j++) {
                mma16816(d[i][j], ah[i], bh[j]);
                mma16816(d[i][j], ah[i], bl[j]);
                mma16816(d[i][j], al[i], bh[j]);
            }
        __syncthreads();
    }

    #pragma unroll
    for (int i = 0; i < MT; i++) {
        int row0 = m0 + m0w + 16 * i + gr;
        int row1 = row0 + 8;
        #pragma unroll
        for (int j = 0; j < NT; j++) {
            int col = n0 + n0w + 8 * j + 2 * thc;
            float b0 = bias[col], b1 = bias[col + 1];
            float v00 = d[i][j][0] + b0, v01 = d[i][j][1] + b1;
            float v10 = d[i][j][2] + b0, v11 = d[i][j][3] + b1;
            if (RELU) {
                v00 = fmaxf(v00, 0.0f); v01 = fmaxf(v01, 0.0f);
                v10 = fmaxf(v10, 0.0f); v11 = fmaxf(v11, 0.0f);
            }
            if (OMODE == 0) {
                if (row0 < M) *(float2*)(outf + (size_t)row0 * ldo_p + col) = make_float2(v00, v01);
                if (row1 < M) *(float2*)(outf + (size_t)row1 * ldo_p + col) = make_float2(v10, v11);
            } else if (OMODE == 1) {
                int pidx = (ocol0 + col) >> 1;
                if (row0 < M) outs[(size_t)row0 * ldo_p + pidx] = splitpair(v00, v01);
                if (row1 < M) outs[(size_t)row1 * ldo_p + pidx] = splitpair(v10, v11);
            } else {
                float* dst = (col < 256) ? outf : outf2;
                int cc = (col < 256) ? col : col - 256;
                if (row0 < M) *(float2*)(dst + (size_t)row0 * 256 + cc) = make_float2(v00, v01);
                if (row1 < M) *(float2*)(dst + (size_t)row1 * 256 + cc) = make_float2(v10, v11);
            }
        }
    }
}

// ---------------- node aggregation: na = sum x[src] (needs only CSR + x) ----------------
__global__ void node_agg_kernel(const float* __restrict__ x) {
    int gw = (blockIdx.x * blockDim.x + threadIdx.x) >> 5;
    int lane = threadIdx.x & 31;
    if (gw >= N_NODESC) return;
    int beg = g_off[gw], end = g_off[gw + 1];
    float4 na = make_float4(0, 0, 0, 0);
    for (int e = beg; e < end; e++) {
        int s = g_csr[e];
        float4 xv = ((const float4*)(x + (size_t)s * 128))[lane];
        na.x += xv.x; na.y += xv.y; na.z += xv.z; na.w += xv.w;
    }
    u64* nw = g_nas + (size_t)gw * 64;
    nw[2 * lane]     = splitpair(na.x, na.y);
    nw[2 * lane + 1] = splitpair(na.z, na.w);
}

// ---------------- edge aggregation: ea = sum relu(A[dst]+B[src]) (needs CSR + AB) ----------------
__global__ void edge_agg_kernel() {
    int gw = (blockIdx.x * blockDim.x + threadIdx.x) >> 5;
    int lane = threadIdx.x & 31;
    if (gw >= N_NODESC) return;
    int beg = g_off[gw], end = g_off[gw + 1];
    const float4* Ar = (const float4*)(g_Aarr + (size_t)gw * 256);
    float4 a0 = Ar[lane], a1 = Ar[32 + lane];
    float4 e0 = make_float4(0, 0, 0, 0), e1 = e0;
    for (int e = beg; e < end; e++) {
        int s = g_csr[e];
        const float4* br = (const float4*)(g_Barr + (size_t)s * 256);
        float4 b0 = br[lane], b1 = br[32 + lane];
        e0.x += fmaxf(a0.x + b0.x, 0.0f);
        e0.y += fmaxf(a0.y + b0.y, 0.0f);
        e0.z += fmaxf(a0.z + b0.z, 0.0f);
        e0.w += fmaxf(a0.w + b0.w, 0.0f);
        e1.x += fmaxf(a1.x + b1.x, 0.0f);
        e1.y += fmaxf(a1.y + b1.y, 0.0f);
        e1.z += fmaxf(a1.z + b1.z, 0.0f);
        e1.w += fmaxf(a1.w + b1.w, 0.0f);
    }
    u64* ew = g_eas + (size_t)gw * 128;
    ew[2 * lane]          = splitpair(e0.x, e0.y);
    ew[2 * lane + 1]      = splitpair(e0.z, e0.w);
    ew[64 + 2 * lane]     = splitpair(e1.x, e1.y);
    ew[64 + 2 * lane + 1] = splitpair(e1.z, e1.w);
}

// ---------------- final sigmoid ----------------
__global__ void sigmoid_kernel(const float* __restrict__ Wf2, const float* __restrict__ bf2,
                               float* __restrict__ out) {
    int gw = (blockIdx.x * blockDim.x + threadIdx.x) >> 5;
    int lane = threadIdx.x & 31;
    if (gw >= N_NODESC) return;
    float t = g_h2[(size_t)gw * 32 + lane] * Wf2[lane];
    #pragma unroll
    for (int o = 16; o; o >>= 1) t += __shfl_xor_sync(0xffffffffu, t, o);
    if (lane == 0) out[gw] = 1.0f / (1.0f + __expf(-(t + bf2[0])));
}

// ---------------- launch (two-branch fork-join; graph-capture-legal) ----------------
extern "C" void kernel_launch(void* const* d_in, const int* in_sizes, int n_in,
                              void* d_out, int out_size) {
    const float* x  = (const float*)d_in[0];
    const void*  ei = d_in[1];
    const float* W_node = (const float*)d_in[3];
    const float* b_node = (const float*)d_in[4];
    const float* W_edge = (const float*)d_in[5];
    const float* b_edge = (const float*)d_in[6];
    const float* W_ed   = (const float*)d_in[7];
    const float* b_ed   = (const float*)d_in[8];
    const float* W_f1   = (const float*)d_in[9];
    const float* b_f1   = (const float*)d_in[10];
    const float* W_f2   = (const float*)d_in[11];
    const float* b_f2   = (const float*)d_in[12];
    float* out = (float*)d_out;

    u64 *pxs, *pnas, *peas, *phs, *pWcs, *pWns, *pWes, *pWfs;
    float *pA, *pB, *pbc, *ph2;
    cudaGetSymbolAddress((void**)&pxs,  g_xs);
    cudaGetSymbolAddress((void**)&pnas, g_nas);
    cudaGetSymbolAddress((void**)&peas, g_eas);
    cudaGetSymbolAddress((void**)&phs,  g_hs);
    cudaGetSymbolAddress((void**)&pWcs, g_Wcs);
    cudaGetSymbolAddress((void**)&pWns, g_Wns);
    cudaGetSymbolAddress((void**)&pWes, g_Wes);
    cudaGetSymbolAddress((void**)&pWfs, g_Wfs);
    cudaGetSymbolAddress((void**)&pA,   g_Aarr);
    cudaGetSymbolAddress((void**)&pB,   g_Barr);
    cudaGetSymbolAddress((void**)&pbc,  g_bc);
    cudaGetSymbolAddress((void**)&ph2,  g_h2);

    const int MB64  = (N_NODESC + 63) / 64;     // 782
    const int MB128 = (N_NODESC + 127) / 128;   // 391

    static cudaStream_t s_aux = 0;
    static cudaEvent_t ev_zero = 0, ev_setup = 0, ev_csr = 0, ev_node = 0;
    if (!s_aux) {
        cudaStreamCreateWithFlags(&s_aux, cudaStreamNonBlocking);
        cudaEventCreateWithFlags(&ev_zero,  cudaEventDisableTiming);
        cudaEventCreateWithFlags(&ev_setup, cudaEventDisableTiming);
        cudaEventCreateWithFlags(&ev_csr,   cudaEventDisableTiming);
        cudaEventCreateWithFlags(&ev_node,  cudaEventDisableTiming);
    }

    // main: zero -> fork
    zero_kernel<<<(N_NODESC + 255) / 256, 256>>>();
    cudaEventRecord(ev_zero, 0);
    cudaStreamWaitEvent(s_aux, ev_zero, 0);

    // main: setup (splits + weights) -> AB GEMM
    setup_kernel<<<SPLITX_BLKS + PREPW_BLKS, 256>>>(x, W_edge, b_edge, W_node, W_ed, W_f1);
    cudaEventRecord(ev_setup, 0);
    mma_gemm<64, 128, 32, 32, false, 2><<<dim3(4, MB64), 256>>>(
        pxs, pWcs, pbc, pA, (u64*)0, pB, 0, 0, N_NODESC, 128, 512);

    // aux: CSR chain -> node_agg -> node GEMM (all hidden under main's AB+edge_agg)
    detect_kernel<<<256, 256, 0, s_aux>>>((const int*)ei);
    conv_hist_kernel<<<(N_EDGESC + 255) / 256, 256, 0, s_aux>>>(ei);
    scan1_kernel<<<SCAN_BLKS, 1024, 0, s_aux>>>();
    scan2_kernel<<<1, 64, 0, s_aux>>>();
    scan3_kernel<<<(N_NODESC + 255) / 256, 256, 0, s_aux>>>();
    scatter_kernel<<<(N_EDGESC + 255) / 256, 256, 0, s_aux>>>();
    cudaEventRecord(ev_csr, s_aux);
    node_agg_kernel<<<(N_NODESC + 7) / 8, 256, 0, s_aux>>>(x);
    cudaStreamWaitEvent(s_aux, ev_setup, 0);   // weights ready before node GEMM
    mma_gemm<64, 128, 32, 32, true, 1><<<dim3(2, MB64), 256, 0, s_aux>>>(
        pnas, pWns, b_node, (float*)0, phs, (float*)0, 192, 0, N_NODESC, 128, 256);
    cudaEventRecord(ev_node, s_aux);

    // main: edge_agg (needs CSR + AB) -> edge GEMM
    cudaStreamWaitEvent(0, ev_csr, 0);
    edge_agg_kernel<<<(N_NODESC + 7) / 8, 256>>>();
    mma_gemm<64, 128, 32, 32, true, 1><<<dim3(1, MB64), 256>>>(
        peas, pWes, b_ed, (float*)0, phs, (float*)0, 192, 256, N_NODESC, 256, 128);

    // join: fuse needs both h halves
    cudaStreamWaitEvent(0, ev_node, 0);
    mma_gemm<128, 32, 32, 16, true, 0><<<dim3(1, MB128), 256>>>(
        phs, pWfs, b_f1, ph2, (u64*)0, (float*)0, 32, 0, N_NODESC, 384, 32);

    sigmoid_kernel<<<(N_NODESC + 7) / 8, 256>>>(W_f2, b_f2, out);
}